// round 3
// baseline (speedup 1.0000x reference)
#include <cuda_runtime.h>
#include <cuda_bf16.h>
#include <cstdint>

#define NMAX 200000
#define PCAP 65536

// ---------------- device scratch (static, no runtime allocation) ----------
__device__ __nv_bfloat16 g_h1[(size_t)NMAX * 256];    // layer-1 output, bf16
__device__ float         g_acc[(size_t)NMAX * 256];   // layer-2 pre-relu accumulator
__device__ __nv_bfloat16 g_w2hi[9 * 256 * 256];       // W2^T hi: [k][cout][cin]
__device__ __nv_bfloat16 g_w2lo[9 * 256 * 256];       // W2^T lo residual
__device__ int  g_src[9][PCAP];
__device__ int  g_dst[9][PCAP];
__device__ int  g_cnt[9];
__device__ float g_counts[8];

// ---------------- prep: zero output, counters ----------------------------
__global__ void prep_kernel(float* out) {
    int t = threadIdx.x;
    for (int i = t; i < 2048; i += blockDim.x) out[i] = 0.f;
    if (t < 9) g_cnt[t] = 0;
    if (t < 8) g_counts[t] = 0.f;
}

// ---------------- W2 transpose + split double-bf16 convert ----------------
__global__ void convw2_kernel(const float* __restrict__ W2) {
    int e = blockIdx.x * blockDim.x + threadIdx.x;
    if (e < 9 * 256 * 256) {
        int k = e >> 16, co = (e >> 8) & 255, ci = e & 255;
        float w = W2[(k << 16) + (ci << 8) + co];
        __nv_bfloat16 hi = __float2bfloat16(w);
        float lo = w - __bfloat162float(hi);
        g_w2hi[e] = hi;
        g_w2lo[e] = __float2bfloat16(lo);
    }
}

// ---------------- layer 1 (Cin=3) + pair-list build -----------------------
__global__ void layer1_kernel(const float* __restrict__ feats,
                              const float* __restrict__ W1,
                              const int* __restrict__ nbr, int n) {
    int i = blockIdx.x;
    int c = threadIdx.x;                 // 256 threads = 256 output channels
    __shared__ float f[9][3];
    __shared__ int   vk[9];
    if (c < 9) {
        int j = nbr[(size_t)i * 9 + c];
        vk[c] = j;
        if (j >= 0) {
            f[c][0] = feats[(size_t)j * 3 + 0];
            f[c][1] = feats[(size_t)j * 3 + 1];
            f[c][2] = feats[(size_t)j * 3 + 2];
            if (c != 4) {   // emit off-center pair (k, src=j, dst=i)
                int pos = atomicAdd(&g_cnt[c], 1);
                if (pos < PCAP) { g_src[c][pos] = j; g_dst[c][pos] = i; }
            }
        }
    }
    __syncthreads();
    float acc = 0.f;
    #pragma unroll
    for (int k = 0; k < 9; k++) {
        if (vk[k] >= 0) {
            acc += f[k][0] * W1[(k * 3 + 0) * 256 + c]
                 + f[k][1] * W1[(k * 3 + 1) * 256 + c]
                 + f[k][2] * W1[(k * 3 + 2) * 256 + c];
        }
    }
    g_h1[(size_t)i * 256 + c] = __float2bfloat16(acc > 0.f ? acc : 0.f);
}

// ---------------- bf16 tensor-core GEMM, split-B double-bf16 --------------
#define KC 16
#define LDS_A 24   // bf16 elems per row (16 + 8 pad) -> conflict-free frag LDS
#define LDS_B 24

__device__ __forceinline__ void mma16816(float c[4], const uint32_t a[4],
                                         const uint32_t b[2]) {
    asm volatile(
        "mma.sync.aligned.m16n8k16.row.col.f32.bf16.bf16.f32 "
        "{%0,%1,%2,%3}, {%4,%5,%6,%7}, {%8,%9}, {%0,%1,%2,%3};\n"
        : "+f"(c[0]), "+f"(c[1]), "+f"(c[2]), "+f"(c[3])
        : "r"(a[0]), "r"(a[1]), "r"(a[2]), "r"(a[3]), "r"(b[0]), "r"(b[1]));
}

__device__ __forceinline__ void red_v2(float* p, float v0, float v1) {
    asm volatile("red.global.add.v2.f32 [%0], {%1,%2};"
                 :: "l"(p), "f"(v0), "f"(v1) : "memory");
}

// C_tile[128 x 256] += A(gathered rows)[128 x 256] @ (W2hi+W2lo)[k]^T
__global__ __launch_bounds__(256) void gemm_kernel(int n, int self) {
    __shared__ __nv_bfloat16 As [128 * LDS_A];
    __shared__ __nv_bfloat16 BsH[256 * LDS_B];
    __shared__ __nv_bfloat16 BsL[256 * LDS_B];
    int tid = threadIdx.x, lane = tid & 31, warp = tid >> 5;
    int wm = warp >> 2, wn = warp & 3;     // 2x4 warp grid -> 64x64 per warp
    int g = lane >> 2, t = lane & 3;

    int kk, tiles, cnt = 0;
    const int* srcl = nullptr; const int* dstl = nullptr;
    if (self) {
        kk = 4;
        tiles = (n + 127) >> 7;
    } else {
        int y = blockIdx.y;
        kk = (y < 4) ? y : y + 1;          // skip k=4
        cnt = g_cnt[kk]; if (cnt > PCAP) cnt = PCAP;
        tiles = (cnt + 127) >> 7;
        srcl = g_src[kk]; dstl = g_dst[kk];
    }
    const __nv_bfloat16* BH = g_w2hi + (size_t)kk * 65536;
    const __nv_bfloat16* BL = g_w2lo + (size_t)kk * 65536;

    for (int tile = blockIdx.x; tile < tiles; tile += gridDim.x) {
        float acc[4][8][4];
        #pragma unroll
        for (int a = 0; a < 4; a++)
            #pragma unroll
            for (int b = 0; b < 8; b++)
                #pragma unroll
                for (int d = 0; d < 4; d++) acc[a][b][d] = 0.f;

        for (int kc = 0; kc < 256; kc += KC) {
            __syncthreads();
            // A chunk: 128 rows x 16 cols (gather) -> 256 uint4, 1/thread
            {
                int r = tid >> 1, q = tid & 1;
                int ridx = tile * 128 + r;
                uint4 v = make_uint4(0, 0, 0, 0);
                if (self) {
                    if (ridx < n)
                        v = *(const uint4*)(g_h1 + (size_t)ridx * 256 + kc + q * 8);
                } else if (ridx < cnt) {
                    int s = srcl[ridx];
                    v = *(const uint4*)(g_h1 + (size_t)s * 256 + kc + q * 8);
                }
                *(uint4*)(As + r * LDS_A + q * 8) = v;
            }
            // B chunks: 256 rows x 16 cols, hi + lo -> 512 uint4 each
            #pragma unroll
            for (int e = 0; e < 2; e++) {
                int ee = tid + e * 256;
                int r = ee >> 1, q = ee & 1;
                *(uint4*)(BsH + r * LDS_B + q * 8) =
                    *(const uint4*)(BH + r * 256 + kc + q * 8);
                *(uint4*)(BsL + r * LDS_B + q * 8) =
                    *(const uint4*)(BL + r * 256 + kc + q * 8);
            }
            __syncthreads();
            // one m16n8k16 K-step per chunk
            uint32_t afr[4][4];
            #pragma unroll
            for (int mi = 0; mi < 4; mi++) {
                const __nv_bfloat16* ap =
                    As + (wm * 64 + mi * 16 + g) * LDS_A + 2 * t;
                afr[mi][0] = *(const uint32_t*)ap;
                afr[mi][1] = *(const uint32_t*)(ap + 8 * LDS_A);
                afr[mi][2] = *(const uint32_t*)(ap + 8);
                afr[mi][3] = *(const uint32_t*)(ap + 8 * LDS_A + 8);
            }
            #pragma unroll
            for (int ni = 0; ni < 8; ni++) {
                int nrow = wn * 64 + ni * 8 + g;
                uint32_t bh[2], bl[2];
                const __nv_bfloat16* bp = BsH + nrow * LDS_B + 2 * t;
                bh[0] = *(const uint32_t*)bp;
                bh[1] = *(const uint32_t*)(bp + 8);
                const __nv_bfloat16* bq = BsL + nrow * LDS_B + 2 * t;
                bl[0] = *(const uint32_t*)bq;
                bl[1] = *(const uint32_t*)(bq + 8);
                #pragma unroll
                for (int mi = 0; mi < 4; mi++) {
                    mma16816(acc[mi][ni], afr[mi], bh);
                    mma16816(acc[mi][ni], afr[mi], bl);
                }
            }
        }
        // epilogue
        #pragma unroll
        for (int mi = 0; mi < 4; mi++) {
            int r0 = wm * 64 + mi * 16 + g;
            #pragma unroll
            for (int ni = 0; ni < 8; ni++) {
                int col = wn * 64 + ni * 8 + 2 * t;
                int ra = tile * 128 + r0, rb = ra + 8;
                if (self) {
                    if (ra < n)
                        *(float2*)(g_acc + (size_t)ra * 256 + col) =
                            make_float2(acc[mi][ni][0], acc[mi][ni][1]);
                    if (rb < n)
                        *(float2*)(g_acc + (size_t)rb * 256 + col) =
                            make_float2(acc[mi][ni][2], acc[mi][ni][3]);
                } else {
                    if (ra < cnt) {
                        int d = dstl[ra];
                        red_v2(g_acc + (size_t)d * 256 + col,
                               acc[mi][ni][0], acc[mi][ni][1]);
                    }
                    if (rb < cnt) {
                        int d = dstl[rb];
                        red_v2(g_acc + (size_t)d * 256 + col,
                               acc[mi][ni][2], acc[mi][ni][3]);
                    }
                }
            }
        }
    }
}

// ---------------- relu + per-batch mean pooling ----------------------------
__global__ void pool_kernel(const int* __restrict__ batch_ids,
                            float* out, int n) {
    int i0 = blockIdx.x * 256;
    int c = threadIdx.x;
    __shared__ int sb[256];
    int ii = i0 + c;
    sb[c] = (ii < n) ? batch_ids[ii] : -1;
    __syncthreads();
    float sum = 0.f;
    int cur = sb[0];
    for (int r = 0; r < 256; r++) {
        int b = sb[r];
        if (b < 0) break;
        if (b != cur) { atomicAdd(&out[cur * 256 + c], sum); sum = 0.f; cur = b; }
        float v = g_acc[(size_t)(i0 + r) * 256 + c];
        sum += (v > 0.f ? v : 0.f);
    }
    if (cur >= 0) atomicAdd(&out[cur * 256 + c], sum);
    if (c == 0) {
        int cnt_ = 0; int cb = sb[0];
        for (int r = 0; r < 256; r++) {
            int b = sb[r]; if (b < 0) break;
            if (b != cb) { atomicAdd(&g_counts[cb], (float)cnt_); cnt_ = 0; cb = b; }
            cnt_++;
        }
        if (cb >= 0) atomicAdd(&g_counts[cb], (float)cnt_);
    }
}

__global__ void finalize_kernel(float* out) {
    int e = blockIdx.x * 256 + threadIdx.x;
    if (e < 2048) {
        float cd = g_counts[e >> 8];
        out[e] = out[e] / cd;
    }
}

// ---------------- launch ----------------------------------------------------
extern "C" void kernel_launch(void* const* d_in, const int* in_sizes, int n_in,
                              void* d_out, int out_size) {
    const float* feats = (const float*)d_in[0];
    const float* W1    = (const float*)d_in[1];
    const float* W2    = (const float*)d_in[2];
    const int*   nbr   = (const int*)d_in[3];
    const int*   bids  = (const int*)d_in[4];
    int n = in_sizes[0] / 3;
    float* out = (float*)d_out;

    prep_kernel<<<1, 1024>>>(out);
    convw2_kernel<<<(9 * 256 * 256 + 255) / 256, 256>>>(W2);
    layer1_kernel<<<n, 256>>>(feats, W1, nbr, n);
    gemm_kernel<<<dim3(444, 1), 256>>>(n, 1);   // dense self tap (k=4), plain stores
    gemm_kernel<<<dim3(40, 8), 256>>>(n, 0);    // 8 off-center taps, atomic scatter
    pool_kernel<<<(n + 255) / 256, 256>>>(bids, out, n);
    finalize_kernel<<<8, 256>>>(out);
}

// round 4
// speedup vs baseline: 1.3977x; 1.3977x over previous
#include <cuda_runtime.h>
#include <cuda_bf16.h>
#include <cstdint>

#define NMAX 200000
#define PCAP 65536
#define LDS_A 24   // 16 K-elems + 8 pad (12 words/row: conflict-free frag LDS)

// ---------------- device scratch ----------------
__device__ __nv_bfloat16 g_h1[(size_t)NMAX * 256];
__device__ float         g_acc[(size_t)NMAX * 256];   // sparse-tap accumulator (flagged rows only)
__device__ __nv_bfloat16 g_w2hi[9 * 256 * 256];       // W2^T hi [k][cout][cin]
__device__ __nv_bfloat16 g_w2lo[9 * 256 * 256];       // W2^T lo residual
__device__ int  g_src[9][PCAP];
__device__ int  g_dst[9][PCAP];
__device__ int  g_cnt[9];
__device__ float g_counts[8];
__device__ unsigned char g_flag[NMAX];                // row has >=1 off-center neighbor

// ---------------- prep ----------------
__global__ void prep_kernel(float* out) {
    int t = blockIdx.x * blockDim.x + threadIdx.x;
    int stride = gridDim.x * blockDim.x;
    for (int i = t; i < 2048; i += stride) out[i] = 0.f;
    for (int i = t; i < NMAX / 4; i += stride) ((int*)g_flag)[i] = 0;
    if (t < 9) g_cnt[t] = 0;
    if (t < 8) g_counts[t] = 0.f;
}

// ---------------- W2 transpose + split double-bf16 ----------------
__global__ void convw2_kernel(const float* __restrict__ W2) {
    int e = blockIdx.x * blockDim.x + threadIdx.x;
    if (e < 9 * 256 * 256) {
        int k = e >> 16, co = (e >> 8) & 255, ci = e & 255;
        float w = W2[(k << 16) + (ci << 8) + co];
        __nv_bfloat16 hi = __float2bfloat16(w);
        g_w2hi[e] = hi;
        g_w2lo[e] = __float2bfloat16(w - __bfloat162float(hi));
    }
}

// ---------------- layer 1: warp per point ----------------
__global__ void layer1_kernel(const float* __restrict__ feats,
                              const float* __restrict__ W1,
                              const int* __restrict__ nbr, int n) {
    int gw = (blockIdx.x * blockDim.x + threadIdx.x) >> 5;
    int lane = threadIdx.x & 31;
    int nw = (gridDim.x * blockDim.x) >> 5;
    for (int i = gw; i < n; i += nw) {
        int j = -1; float f0 = 0.f, f1 = 0.f, f2 = 0.f;
        if (lane < 9) {
            j = nbr[(size_t)i * 9 + lane];
            if (j >= 0) {
                f0 = feats[(size_t)j * 3 + 0];
                f1 = feats[(size_t)j * 3 + 1];
                f2 = feats[(size_t)j * 3 + 2];
            }
        }
        unsigned vm = __ballot_sync(0xffffffffu, lane < 9 && j >= 0);
        if (lane < 9 && j >= 0 && lane != 4) {
            int pos = atomicAdd(&g_cnt[lane], 1);
            if (pos < PCAP) { g_src[lane][pos] = j; g_dst[lane][pos] = i; }
        }
        if (lane == 0) g_flag[i] = (vm & 0x1EFu) ? 1 : 0;
        float acc[8];
        #pragma unroll
        for (int q = 0; q < 8; q++) acc[q] = 0.f;
        int c0 = lane * 8;
        #pragma unroll
        for (int k = 0; k < 9; k++) {
            if (vm & (1u << k)) {          // warp-uniform branch
                float a0 = __shfl_sync(0xffffffffu, f0, k);
                float a1 = __shfl_sync(0xffffffffu, f1, k);
                float a2 = __shfl_sync(0xffffffffu, f2, k);
                const float4* w0 = (const float4*)(W1 + (k * 3 + 0) * 256 + c0);
                const float4* w1 = (const float4*)(W1 + (k * 3 + 1) * 256 + c0);
                const float4* w2 = (const float4*)(W1 + (k * 3 + 2) * 256 + c0);
                float4 x0 = w0[0], x1 = w0[1];
                float4 y0 = w1[0], y1 = w1[1];
                float4 z0 = w2[0], z1 = w2[1];
                acc[0] += a0 * x0.x + a1 * y0.x + a2 * z0.x;
                acc[1] += a0 * x0.y + a1 * y0.y + a2 * z0.y;
                acc[2] += a0 * x0.z + a1 * y0.z + a2 * z0.z;
                acc[3] += a0 * x0.w + a1 * y0.w + a2 * z0.w;
                acc[4] += a0 * x1.x + a1 * y1.x + a2 * z1.x;
                acc[5] += a0 * x1.y + a1 * y1.y + a2 * z1.y;
                acc[6] += a0 * x1.z + a1 * y1.z + a2 * z1.z;
                acc[7] += a0 * x1.w + a1 * y1.w + a2 * z1.w;
            }
        }
        __nv_bfloat162 o[4];
        #pragma unroll
        for (int q = 0; q < 4; q++) {
            float u = acc[2 * q],     v = acc[2 * q + 1];
            o[q] = __floats2bfloat162_rn(u > 0.f ? u : 0.f, v > 0.f ? v : 0.f);
        }
        *(uint4*)(g_h1 + (size_t)i * 256 + c0) = *(uint4*)o;
    }
}

// ---------------- zero g_acc rows that will receive sparse adds -----------
__global__ void zero_rows_kernel() {
    int tap = blockIdx.y;
    int kk = (tap < 4) ? tap : tap + 1;
    int cnt = g_cnt[kk]; if (cnt > PCAP) cnt = PCAP;
    float4 z = make_float4(0.f, 0.f, 0.f, 0.f);
    for (int p = blockIdx.x; p < cnt; p += gridDim.x) {
        int row = g_dst[kk][p];
        float4* dst = (float4*)(g_acc + (size_t)row * 256);
        for (int e = threadIdx.x; e < 64; e += blockDim.x) dst[e] = z;
    }
}

// ---------------- GEMM: 128x128 tile, cp.async double-buffer --------------
__device__ __forceinline__ void mma16816(float c[4], const uint32_t a[4],
                                         const uint32_t b[2]) {
    asm volatile(
        "mma.sync.aligned.m16n8k16.row.col.f32.bf16.bf16.f32 "
        "{%0,%1,%2,%3}, {%4,%5,%6,%7}, {%8,%9}, {%0,%1,%2,%3};\n"
        : "+f"(c[0]), "+f"(c[1]), "+f"(c[2]), "+f"(c[3])
        : "r"(a[0]), "r"(a[1]), "r"(a[2]), "r"(a[3]), "r"(b[0]), "r"(b[1]));
}
__device__ __forceinline__ void red_v2(float* p, float v0, float v1) {
    asm volatile("red.global.add.v2.f32 [%0], {%1,%2};"
                 :: "l"(p), "f"(v0), "f"(v1) : "memory");
}
__device__ __forceinline__ void cp16(uint32_t saddr, const void* g, bool valid) {
    int sz = valid ? 16 : 0;
    asm volatile("cp.async.cg.shared.global [%0], [%1], 16, %2;"
                 :: "r"(saddr), "l"(g), "r"(sz));
}

#define STAGE_BYTES 18432   // A(6144) + BH(6144) + BL(6144)

__global__ __launch_bounds__(256, 2) void gemm_kernel(int n, int self,
                                                      const int* __restrict__ bids,
                                                      float* __restrict__ out) {
    __shared__ __align__(16) char s_raw[2 * STAGE_BYTES + 512];
    int tid = threadIdx.x, lane = tid & 31, warp = tid >> 5;
    int wm = warp >> 2, wn = warp & 3;   // 2 x 4 warps -> warp tile 64M x 32N
    int g = lane >> 2, t = lane & 3;

    int kk, tiles, cnt = 0, nhalf;
    const int* srcl = nullptr; const int* dstl = nullptr;
    if (self) {
        kk = 4; nhalf = blockIdx.y;
        tiles = (n + 127) >> 7;
    } else {
        int y = blockIdx.y;
        int tap = y >> 1; nhalf = y & 1;
        kk = (tap < 4) ? tap : tap + 1;
        cnt = g_cnt[kk]; if (cnt > PCAP) cnt = PCAP;
        tiles = (cnt + 127) >> 7;
        srcl = g_src[kk]; dstl = g_dst[kk];
    }
    const __nv_bfloat16* BH = g_w2hi + (size_t)kk * 65536 + (size_t)nhalf * 128 * 256;
    const __nv_bfloat16* BL = g_w2lo + (size_t)kk * 65536 + (size_t)nhalf * 128 * 256;

    uint32_t sbase = (uint32_t)__cvta_generic_to_shared(s_raw);
    int r_ld = tid >> 1, q_ld = tid & 1;           // per-thread cp.async coords

    for (int tile = blockIdx.x; tile < tiles; tile += gridDim.x) {
        float acc[4][4][4];
        #pragma unroll
        for (int a = 0; a < 4; a++)
            #pragma unroll
            for (int b = 0; b < 4; b++)
                #pragma unroll
                for (int d = 0; d < 4; d++) acc[a][b][d] = 0.f;

        // resolve this thread's A-row source index once per tile
        int arow = tile * 128 + r_ld;
        const __nv_bfloat16* asrc = nullptr;
        bool avalid;
        if (self) {
            avalid = (arow < n);
            if (avalid) asrc = g_h1 + (size_t)arow * 256;
        } else {
            avalid = (arow < cnt);
            if (avalid) asrc = g_h1 + (size_t)srcl[arow] * 256;
        }

        // pipeline
        #pragma unroll 1
        for (int c = 0; c < 17; c++) {
            if (c < 16) {               // issue loads for chunk c into stage c&1
                int kc = c * 16;
                uint32_t sa = sbase + (c & 1) * STAGE_BYTES;
                cp16(sa + (r_ld * LDS_A + q_ld * 8) * 2,
                     asrc + kc + q_ld * 8, avalid);
                cp16(sa + 6144 + (r_ld * LDS_A + q_ld * 8) * 2,
                     BH + r_ld * 256 + kc + q_ld * 8, true);
                cp16(sa + 12288 + (r_ld * LDS_A + q_ld * 8) * 2,
                     BL + r_ld * 256 + kc + q_ld * 8, true);
            }
            asm volatile("cp.async.commit_group;");
            if (c == 0) continue;       // nothing to compute yet
            if (c < 16) asm volatile("cp.async.wait_group 1;");
            else        asm volatile("cp.async.wait_group 0;");
            __syncthreads();
            // compute chunk c-1 from stage (c-1)&1
            {
                const __nv_bfloat16* As  = (const __nv_bfloat16*)(s_raw + ((c - 1) & 1) * STAGE_BYTES);
                const __nv_bfloat16* BsH = As + 3072;
                const __nv_bfloat16* BsL = As + 6144;
                uint32_t afr[4][4];
                #pragma unroll
                for (int mi = 0; mi < 4; mi++) {
                    const __nv_bfloat16* ap = As + (wm * 64 + mi * 16 + g) * LDS_A + 2 * t;
                    afr[mi][0] = *(const uint32_t*)ap;
                    afr[mi][1] = *(const uint32_t*)(ap + 8 * LDS_A);
                    afr[mi][2] = *(const uint32_t*)(ap + 8);
                    afr[mi][3] = *(const uint32_t*)(ap + 8 * LDS_A + 8);
                }
                #pragma unroll
                for (int ni = 0; ni < 4; ni++) {
                    int nrow = wn * 32 + ni * 8 + g;
                    uint32_t bh[2], bl[2];
                    const __nv_bfloat16* bp = BsH + nrow * LDS_A + 2 * t;
                    bh[0] = *(const uint32_t*)bp;
                    bh[1] = *(const uint32_t*)(bp + 8);
                    const __nv_bfloat16* bq = BsL + nrow * LDS_A + 2 * t;
                    bl[0] = *(const uint32_t*)bq;
                    bl[1] = *(const uint32_t*)(bq + 8);
                    #pragma unroll
                    for (int mi = 0; mi < 4; mi++) {
                        mma16816(acc[mi][ni], afr[mi], bh);
                        mma16816(acc[mi][ni], afr[mi], bl);
                    }
                }
            }
            __syncthreads();
        }

        if (!self) {
            // scatter into g_acc via reduction atomics
            #pragma unroll
            for (int mi = 0; mi < 4; mi++) {
                int r0 = wm * 64 + mi * 16 + g;
                #pragma unroll
                for (int ni = 0; ni < 4; ni++) {
                    int col = nhalf * 128 + wn * 32 + ni * 8 + 2 * t;
                    int ra = tile * 128 + r0, rb = ra + 8;
                    if (ra < cnt)
                        red_v2(g_acc + (size_t)dstl[ra] * 256 + col,
                               acc[mi][ni][0], acc[mi][ni][1]);
                    if (rb < cnt)
                        red_v2(g_acc + (size_t)dstl[rb] * 256 + col,
                               acc[mi][ni][2], acc[mi][ni][3]);
                }
            }
        } else {
            // fused: add sparse acc (flagged rows), relu, pooled reduce
            float* tilebuf = (float*)s_raw;              // [128][66]
            int*   sbatch  = (int*)(s_raw + 2 * STAGE_BYTES);
            __syncthreads();
            if (tid < 128) {
                int r = tile * 128 + tid;
                sbatch[tid] = (r < n) ? bids[r] : -1;
            }
            #pragma unroll
            for (int h = 0; h < 2; h++) {
                __syncthreads();
                if ((wn >> 1) == h) {
                    #pragma unroll
                    for (int mi = 0; mi < 4; mi++) {
                        int rl0 = wm * 64 + mi * 16 + g;
                        #pragma unroll
                        for (int ni = 0; ni < 4; ni++) {
                            int cl = (wn & 1) * 32 + ni * 8 + 2 * t;   // 0..63
                            int gcol = nhalf * 128 + h * 64 + cl;
                            int ra = tile * 128 + rl0, rb = ra + 8;
                            float v0 = acc[mi][ni][0], v1 = acc[mi][ni][1];
                            float v2 = acc[mi][ni][2], v3 = acc[mi][ni][3];
                            if (ra < n && g_flag[ra]) {
                                float2 s = *(float2*)(g_acc + (size_t)ra * 256 + gcol);
                                v0 += s.x; v1 += s.y;
                            }
                            if (rb < n && g_flag[rb]) {
                                float2 s = *(float2*)(g_acc + (size_t)rb * 256 + gcol);
                                v2 += s.x; v3 += s.y;
                            }
                            tilebuf[rl0 * 66 + cl] = v0;
                            tilebuf[rl0 * 66 + cl + 1] = v1;
                            tilebuf[(rl0 + 8) * 66 + cl] = v2;
                            tilebuf[(rl0 + 8) * 66 + cl + 1] = v3;
                        }
                    }
                }
                __syncthreads();
                if (tid < 64) {
                    int c = tid;
                    float sum = 0.f; int cur = sbatch[0];
                    #pragma unroll 4
                    for (int r = 0; r < 128; r++) {
                        int b = sbatch[r];
                        if (b != cur) {
                            if (cur >= 0)
                                atomicAdd(&out[cur * 256 + nhalf * 128 + h * 64 + c], sum);
                            sum = 0.f; cur = b;
                        }
                        if (b >= 0) {
                            float v = tilebuf[r * 66 + c];
                            sum += (v > 0.f ? v : 0.f);
                        }
                    }
                    if (cur >= 0)
                        atomicAdd(&out[cur * 256 + nhalf * 128 + h * 64 + c], sum);
                }
            }
            __syncthreads();   // smem reused by next tile's pipeline
        }
    }
}

// ---------------- batch counts + finalize ----------------
__global__ void count_kernel(const int* __restrict__ bids, int n) {
    __shared__ int loc[8];
    if (threadIdx.x < 8) loc[threadIdx.x] = 0;
    __syncthreads();
    for (int i = blockIdx.x * blockDim.x + threadIdx.x; i < n;
         i += gridDim.x * blockDim.x)
        atomicAdd(&loc[bids[i]], 1);
    __syncthreads();
    if (threadIdx.x < 8) atomicAdd(&g_counts[threadIdx.x], (float)loc[threadIdx.x]);
}

__global__ void finalize_kernel(float* out) {
    int e = blockIdx.x * 256 + threadIdx.x;
    if (e < 2048) out[e] = out[e] / g_counts[e >> 8];
}

// ---------------- launch ----------------
extern "C" void kernel_launch(void* const* d_in, const int* in_sizes, int n_in,
                              void* d_out, int out_size) {
    const float* feats = (const float*)d_in[0];
    const float* W1    = (const float*)d_in[1];
    const float* W2    = (const float*)d_in[2];
    const int*   nbr   = (const int*)d_in[3];
    const int*   bids  = (const int*)d_in[4];
    int n = in_sizes[0] / 3;
    float* out = (float*)d_out;

    prep_kernel<<<64, 256>>>(out);
    convw2_kernel<<<(9 * 256 * 256 + 255) / 256, 256>>>(W2);
    layer1_kernel<<<2048, 256>>>(feats, W1, nbr, n);
    zero_rows_kernel<<<dim3(256, 8), 64>>>();
    gemm_kernel<<<dim3(40, 16), 256>>>(n, 0, bids, out);            // 8 taps x 2 N-halves
    gemm_kernel<<<dim3((n + 127) / 128, 2), 256>>>(n, 1, bids, out); // self + fused pool
    count_kernel<<<128, 256>>>(bids, n);
    finalize_kernel<<<8, 256>>>(out);
}

// round 5
// speedup vs baseline: 1.6012x; 1.1456x over previous
#include <cuda_runtime.h>
#include <cuda_fp16.h>
#include <cstdint>

#define NMAX 200000
#define PCAP 65536
#define LDS_A 24   // 16 K-elems + 8 pad -> conflict-free frag LDS

// ---------------- device scratch ----------------
__device__ __half g_h1[(size_t)NMAX * 256];
__device__ float  g_acc[(size_t)NMAX * 256];   // sparse-tap accumulator (flagged rows)
__device__ __half g_w2t[9 * 256 * 256];        // W2^T fp16 [k][cout][cin]
__device__ int  g_src[9][PCAP];
__device__ int  g_dst[9][PCAP];
__device__ int  g_cnt[9];
__device__ float g_counts[8];
__device__ unsigned char g_flag[NMAX];

// ---------------- prep ----------------
__global__ void prep_kernel(float* out) {
    int t = blockIdx.x * blockDim.x + threadIdx.x;
    int stride = gridDim.x * blockDim.x;
    for (int i = t; i < 2048; i += stride) out[i] = 0.f;
    for (int i = t; i < NMAX / 4; i += stride) ((int*)g_flag)[i] = 0;
    if (t < 9) g_cnt[t] = 0;
    if (t < 8) g_counts[t] = 0.f;
}

// ---------------- W2 transpose -> fp16 ----------------
__global__ void convw2_kernel(const float* __restrict__ W2) {
    int e = blockIdx.x * blockDim.x + threadIdx.x;
    if (e < 9 * 256 * 256) {
        int k = e >> 16, co = (e >> 8) & 255, ci = e & 255;
        g_w2t[e] = __float2half_rn(W2[(k << 16) + (ci << 8) + co]);
    }
}

// ---------------- layer 1: warp per point ----------------
__global__ void layer1_kernel(const float* __restrict__ feats,
                              const float* __restrict__ W1,
                              const int* __restrict__ nbr, int n) {
    int gw = (blockIdx.x * blockDim.x + threadIdx.x) >> 5;
    int lane = threadIdx.x & 31;
    int nw = (gridDim.x * blockDim.x) >> 5;
    for (int i = gw; i < n; i += nw) {
        int j = -1; float f0 = 0.f, f1 = 0.f, f2 = 0.f;
        if (lane < 9) {
            j = nbr[(size_t)i * 9 + lane];
            if (j >= 0) {
                f0 = feats[(size_t)j * 3 + 0];
                f1 = feats[(size_t)j * 3 + 1];
                f2 = feats[(size_t)j * 3 + 2];
            }
        }
        unsigned vm = __ballot_sync(0xffffffffu, lane < 9 && j >= 0);
        if (lane < 9 && j >= 0 && lane != 4) {
            int pos = atomicAdd(&g_cnt[lane], 1);
            if (pos < PCAP) { g_src[lane][pos] = j; g_dst[lane][pos] = i; }
        }
        if (lane == 0) g_flag[i] = (vm & 0x1EFu) ? 1 : 0;
        float acc[8];
        #pragma unroll
        for (int q = 0; q < 8; q++) acc[q] = 0.f;
        int c0 = lane * 8;
        #pragma unroll
        for (int k = 0; k < 9; k++) {
            if (vm & (1u << k)) {
                float a0 = __shfl_sync(0xffffffffu, f0, k);
                float a1 = __shfl_sync(0xffffffffu, f1, k);
                float a2 = __shfl_sync(0xffffffffu, f2, k);
                const float4* w0 = (const float4*)(W1 + (k * 3 + 0) * 256 + c0);
                const float4* w1 = (const float4*)(W1 + (k * 3 + 1) * 256 + c0);
                const float4* w2 = (const float4*)(W1 + (k * 3 + 2) * 256 + c0);
                float4 x0 = w0[0], x1 = w0[1];
                float4 y0 = w1[0], y1 = w1[1];
                float4 z0 = w2[0], z1 = w2[1];
                acc[0] += a0 * x0.x + a1 * y0.x + a2 * z0.x;
                acc[1] += a0 * x0.y + a1 * y0.y + a2 * z0.y;
                acc[2] += a0 * x0.z + a1 * y0.z + a2 * z0.z;
                acc[3] += a0 * x0.w + a1 * y0.w + a2 * z0.w;
                acc[4] += a0 * x1.x + a1 * y1.x + a2 * z1.x;
                acc[5] += a0 * x1.y + a1 * y1.y + a2 * z1.y;
                acc[6] += a0 * x1.z + a1 * y1.z + a2 * z1.z;
                acc[7] += a0 * x1.w + a1 * y1.w + a2 * z1.w;
            }
        }
        __half2 o[4];
        #pragma unroll
        for (int q = 0; q < 4; q++) {
            float u = acc[2 * q],     v = acc[2 * q + 1];
            o[q] = __floats2half2_rn(u > 0.f ? u : 0.f, v > 0.f ? v : 0.f);
        }
        *(uint4*)(g_h1 + (size_t)i * 256 + c0) = *(uint4*)o;
    }
}

// ---------------- zero g_acc rows that will receive sparse adds -----------
__global__ void zero_rows_kernel() {
    int tap = blockIdx.y;
    int kk = (tap < 4) ? tap : tap + 1;
    int cnt = g_cnt[kk]; if (cnt > PCAP) cnt = PCAP;
    float4 z = make_float4(0.f, 0.f, 0.f, 0.f);
    for (int p = blockIdx.x; p < cnt; p += gridDim.x) {
        int row = g_dst[kk][p];
        float4* dst = (float4*)(g_acc + (size_t)row * 256);
        for (int e = threadIdx.x; e < 64; e += blockDim.x) dst[e] = z;
    }
}

// ---------------- GEMM: fp16, 128x128 tile, cp.async double-buffer --------
__device__ __forceinline__ void mma16816(float c[4], const uint32_t a[4],
                                         const uint32_t b[2]) {
    asm volatile(
        "mma.sync.aligned.m16n8k16.row.col.f32.f16.f16.f32 "
        "{%0,%1,%2,%3}, {%4,%5,%6,%7}, {%8,%9}, {%0,%1,%2,%3};\n"
        : "+f"(c[0]), "+f"(c[1]), "+f"(c[2]), "+f"(c[3])
        : "r"(a[0]), "r"(a[1]), "r"(a[2]), "r"(a[3]), "r"(b[0]), "r"(b[1]));
}
__device__ __forceinline__ void red_v2(float* p, float v0, float v1) {
    asm volatile("red.global.add.v2.f32 [%0], {%1,%2};"
                 :: "l"(p), "f"(v0), "f"(v1) : "memory");
}
__device__ __forceinline__ void cp16(uint32_t saddr, const void* g, bool valid) {
    int sz = valid ? 16 : 0;
    asm volatile("cp.async.cg.shared.global [%0], [%1], 16, %2;"
                 :: "r"(saddr), "l"(g), "r"(sz));
}

#define STAGE_BYTES 12288   // A(6144) + B(6144)
#define SMEM_TOTAL  34816   // >= max(2*STAGE_BYTES, 128*66*4) + 512

__global__ __launch_bounds__(256, 2) void gemm_kernel(int n, int self,
                                                      const int* __restrict__ bids,
                                                      float* __restrict__ out) {
    __shared__ __align__(16) char s_raw[SMEM_TOTAL];
    int tid = threadIdx.x, lane = tid & 31, warp = tid >> 5;
    int wm = warp >> 2, wn = warp & 3;   // 2 x 4 warps -> warp tile 64M x 32N
    int g = lane >> 2, t = lane & 3;

    int kk, tiles, cnt = 0, nhalf, tile0, tstep;
    const int* srcl = nullptr; const int* dstl = nullptr;
    if (self) {
        kk = 4; nhalf = blockIdx.x;          // x fastest: both halves of a tile adjacent -> L2 reuse
        tiles = (n + 127) >> 7;
        tile0 = blockIdx.y; tstep = gridDim.y;
    } else {
        int y = blockIdx.y;
        int tap = y >> 1; nhalf = y & 1;
        kk = (tap < 4) ? tap : tap + 1;
        cnt = g_cnt[kk]; if (cnt > PCAP) cnt = PCAP;
        tiles = (cnt + 127) >> 7;
        srcl = g_src[kk]; dstl = g_dst[kk];
        tile0 = blockIdx.x; tstep = gridDim.x;
    }
    const __half* BW = g_w2t + (size_t)kk * 65536 + (size_t)nhalf * 128 * 256;

    uint32_t sbase = (uint32_t)__cvta_generic_to_shared(s_raw);
    int r_ld = tid >> 1, q_ld = tid & 1;

    for (int tile = tile0; tile < tiles; tile += tstep) {
        float acc[4][4][4];
        #pragma unroll
        for (int a = 0; a < 4; a++)
            #pragma unroll
            for (int b = 0; b < 4; b++)
                #pragma unroll
                for (int d = 0; d < 4; d++) acc[a][b][d] = 0.f;

        int arow = tile * 128 + r_ld;
        const __half* asrc = nullptr;
        bool avalid;
        if (self) {
            avalid = (arow < n);
            if (avalid) asrc = g_h1 + (size_t)arow * 256;
        } else {
            avalid = (arow < cnt);
            if (avalid) asrc = g_h1 + (size_t)srcl[arow] * 256;
        }

        #pragma unroll 1
        for (int c = 0; c < 17; c++) {
            if (c < 16) {
                int kc = c * 16;
                uint32_t sa = sbase + (c & 1) * STAGE_BYTES;
                cp16(sa + (r_ld * LDS_A + q_ld * 8) * 2,
                     asrc + kc + q_ld * 8, avalid);
                cp16(sa + 6144 + (r_ld * LDS_A + q_ld * 8) * 2,
                     BW + r_ld * 256 + kc + q_ld * 8, true);
            }
            asm volatile("cp.async.commit_group;");
            if (c == 0) continue;
            if (c < 16) asm volatile("cp.async.wait_group 1;");
            else        asm volatile("cp.async.wait_group 0;");
            __syncthreads();
            {
                const __half* As = (const __half*)(s_raw + ((c - 1) & 1) * STAGE_BYTES);
                const __half* Bs = As + 3072;
                uint32_t afr[4][4];
                #pragma unroll
                for (int mi = 0; mi < 4; mi++) {
                    const __half* ap = As + (wm * 64 + mi * 16 + g) * LDS_A + 2 * t;
                    afr[mi][0] = *(const uint32_t*)ap;
                    afr[mi][1] = *(const uint32_t*)(ap + 8 * LDS_A);
                    afr[mi][2] = *(const uint32_t*)(ap + 8);
                    afr[mi][3] = *(const uint32_t*)(ap + 8 * LDS_A + 8);
                }
                #pragma unroll
                for (int ni = 0; ni < 4; ni++) {
                    int nrow = wn * 32 + ni * 8 + g;
                    uint32_t bf[2];
                    const __half* bp = Bs + nrow * LDS_A + 2 * t;
                    bf[0] = *(const uint32_t*)bp;
                    bf[1] = *(const uint32_t*)(bp + 8);
                    #pragma unroll
                    for (int mi = 0; mi < 4; mi++)
                        mma16816(acc[mi][ni], afr[mi], bf);
                }
            }
            __syncthreads();
        }

        if (!self) {
            #pragma unroll
            for (int mi = 0; mi < 4; mi++) {
                int r0 = wm * 64 + mi * 16 + g;
                #pragma unroll
                for (int ni = 0; ni < 4; ni++) {
                    int col = nhalf * 128 + wn * 32 + ni * 8 + 2 * t;
                    int ra = tile * 128 + r0, rb = ra + 8;
                    if (ra < cnt)
                        red_v2(g_acc + (size_t)dstl[ra] * 256 + col,
                               acc[mi][ni][0], acc[mi][ni][1]);
                    if (rb < cnt)
                        red_v2(g_acc + (size_t)dstl[rb] * 256 + col,
                               acc[mi][ni][2], acc[mi][ni][3]);
                }
            }
        } else {
            // fused: add sparse acc (flagged rows), relu, pooled reduce
            float* tilebuf = (float*)s_raw;                        // [128][66]
            int*   sbatch  = (int*)(s_raw + SMEM_TOTAL - 512);
            __syncthreads();
            if (tid < 128) {
                int r = tile * 128 + tid;
                sbatch[tid] = (r < n) ? bids[r] : -1;
            }
            #pragma unroll
            for (int h = 0; h < 2; h++) {
                __syncthreads();
                if ((wn >> 1) == h) {
                    #pragma unroll
                    for (int mi = 0; mi < 4; mi++) {
                        int rl0 = wm * 64 + mi * 16 + g;
                        #pragma unroll
                        for (int ni = 0; ni < 4; ni++) {
                            int cl = (wn & 1) * 32 + ni * 8 + 2 * t;   // 0..63
                            int gcol = nhalf * 128 + h * 64 + cl;
                            int ra = tile * 128 + rl0, rb = ra + 8;
                            float v0 = acc[mi][ni][0], v1 = acc[mi][ni][1];
                            float v2 = acc[mi][ni][2], v3 = acc[mi][ni][3];
                            if (ra < n && g_flag[ra]) {
                                float2 s = *(float2*)(g_acc + (size_t)ra * 256 + gcol);
                                v0 += s.x; v1 += s.y;
                            }
                            if (rb < n && g_flag[rb]) {
                                float2 s = *(float2*)(g_acc + (size_t)rb * 256 + gcol);
                                v2 += s.x; v3 += s.y;
                            }
                            tilebuf[rl0 * 66 + cl] = v0;
                            tilebuf[rl0 * 66 + cl + 1] = v1;
                            tilebuf[(rl0 + 8) * 66 + cl] = v2;
                            tilebuf[(rl0 + 8) * 66 + cl + 1] = v3;
                        }
                    }
                }
                __syncthreads();
                if (tid < 64) {
                    int c = tid;
                    float sum = 0.f; int cur = sbatch[0];
                    #pragma unroll 4
                    for (int r = 0; r < 128; r++) {
                        int b = sbatch[r];
                        if (b != cur) {
                            if (cur >= 0)
                                atomicAdd(&out[cur * 256 + nhalf * 128 + h * 64 + c], sum);
                            sum = 0.f; cur = b;
                        }
                        if (b >= 0) {
                            float v = tilebuf[r * 66 + c];
                            sum += (v > 0.f ? v : 0.f);
                        }
                    }
                    if (cur >= 0)
                        atomicAdd(&out[cur * 256 + nhalf * 128 + h * 64 + c], sum);
                }
            }
            __syncthreads();
        }
    }
}

// ---------------- batch counts + finalize ----------------
__global__ void count_kernel(const int* __restrict__ bids, int n) {
    __shared__ int loc[8];
    if (threadIdx.x < 8) loc[threadIdx.x] = 0;
    __syncthreads();
    for (int i = blockIdx.x * blockDim.x + threadIdx.x; i < n;
         i += gridDim.x * blockDim.x)
        atomicAdd(&loc[bids[i]], 1);
    __syncthreads();
    if (threadIdx.x < 8) atomicAdd(&g_counts[threadIdx.x], (float)loc[threadIdx.x]);
}

__global__ void finalize_kernel(float* out) {
    int e = blockIdx.x * 256 + threadIdx.x;
    if (e < 2048) out[e] = out[e] / g_counts[e >> 8];
}

// ---------------- launch ----------------
extern "C" void kernel_launch(void* const* d_in, const int* in_sizes, int n_in,
                              void* d_out, int out_size) {
    const float* feats = (const float*)d_in[0];
    const float* W1    = (const float*)d_in[1];
    const float* W2    = (const float*)d_in[2];
    const int*   nbr   = (const int*)d_in[3];
    const int*   bids  = (const int*)d_in[4];
    int n = in_sizes[0] / 3;
    float* out = (float*)d_out;

    int tiles = (n + 127) / 128;
    prep_kernel<<<64, 256>>>(out);
    convw2_kernel<<<(9 * 256 * 256 + 255) / 256, 256>>>(W2);
    layer1_kernel<<<2048, 256>>>(feats, W1, nbr, n);
    zero_rows_kernel<<<dim3(256, 8), 64>>>();
    gemm_kernel<<<dim3(40, 16), 256>>>(n, 0, bids, out);        // 8 taps x 2 N-halves
    gemm_kernel<<<dim3(2, tiles), 256>>>(n, 1, bids, out);      // self + fused pool
    count_kernel<<<128, 256>>>(bids, n);
    finalize_kernel<<<8, 256>>>(out);
}